// round 2
// baseline (speedup 1.0000x reference)
#include <cuda_runtime.h>
#include <cuda_bf16.h>
#include <cstdint>

#define N_NODES 100000
#define N_EDGES 3200000
#define F 128

// Scratch for projected features y = x @ W^T  (51.2 MB; y+out ~102MB fits L2)
__device__ float g_y[(size_t)N_NODES * F];

// ---------------------------------------------------------------------------
// Kernel 1: y = x @ W^T      (x: [N,128], W: [128,128] row-major [out,in])
// Each block: 32 rows of x (staged in smem), 128 threads; thread t owns output
// column t and caches W[t][:] in 32 float4 registers.
// ---------------------------------------------------------------------------
__global__ __launch_bounds__(128) void gemm_xWt(const float* __restrict__ x,
                                                const float* __restrict__ W) {
    __shared__ float xs[32 * F];  // 16 KB
    const int t = threadIdx.x;          // 0..127 = output column
    const int row0 = blockIdx.x * 32;

    // Stage 32 rows of x: 4096 floats = 1024 float4, 128 threads -> 8 each
    const float4* x4 = reinterpret_cast<const float4*>(x + (size_t)row0 * F);
    float4* xs4 = reinterpret_cast<float4*>(xs);
#pragma unroll
    for (int i = 0; i < 8; i++) xs4[i * 128 + t] = x4[i * 128 + t];

    // Cache this thread's W row in registers (128 floats)
    const float4* Wrow = reinterpret_cast<const float4*>(W + (size_t)t * F);
    float4 wr[32];
#pragma unroll
    for (int k = 0; k < 32; k++) wr[k] = Wrow[k];

    __syncthreads();

    for (int r = 0; r < 32; r++) {
        const float4* xr = reinterpret_cast<const float4*>(xs + r * F);
        float acc = 0.f;
#pragma unroll
        for (int k = 0; k < 32; k++) {
            float4 xv = xr[k];
            acc += wr[k].x * xv.x + wr[k].y * xv.y + wr[k].z * xv.z + wr[k].w * xv.w;
        }
        g_y[(size_t)(row0 + r) * F + t] = acc;
    }
}

// ---------------------------------------------------------------------------
// Kernel 2: out[i][j] = b[j]   (bias broadcast, float4 stores)
// ---------------------------------------------------------------------------
__global__ void init_bias(const float* __restrict__ b, float* __restrict__ out) {
    const int total = N_NODES * (F / 4);  // 3.2M float4
    int idx = blockIdx.x * blockDim.x + threadIdx.x;
    if (idx < total) {
        const float4* b4 = reinterpret_cast<const float4*>(b);
        reinterpret_cast<float4*>(out)[idx] = b4[idx & (F / 4 - 1)];
    }
}

// ---------------------------------------------------------------------------
// Kernel 3: scatter  out[rows[e]] += vals[e] * y[cols[e]]
// One warp per edge; lane l handles floats [4l, 4l+4). Vector red.
// ---------------------------------------------------------------------------
__global__ __launch_bounds__(256) void spmm_scatter(const int* __restrict__ rows,
                                                    const int* __restrict__ cols,
                                                    const float* __restrict__ vals,
                                                    float* __restrict__ out) {
    const int warp = (blockIdx.x * blockDim.x + threadIdx.x) >> 5;
    const int lane = threadIdx.x & 31;
    if (warp >= N_EDGES) return;

    const int r = rows[warp];
    const int c = cols[warp];
    const float v = vals[warp];

    float4 m = reinterpret_cast<const float4*>(g_y + (size_t)c * F)[lane];
    m.x *= v; m.y *= v; m.z *= v; m.w *= v;

    float* dst = out + (size_t)r * F + lane * 4;
    asm volatile("red.global.add.v4.f32 [%0], {%1,%2,%3,%4};"
                 :: "l"(dst), "f"(m.x), "f"(m.y), "f"(m.z), "f"(m.w)
                 : "memory");
}

// ---------------------------------------------------------------------------
extern "C" void kernel_launch(void* const* d_in, const int* in_sizes, int n_in,
                              void* d_out, int out_size) {
    const int*   L_rows = (const int*)d_in[0];
    const int*   L_cols = (const int*)d_in[1];
    const float* L_vals = (const float*)d_in[2];
    const float* x      = (const float*)d_in[3];
    const float* W      = (const float*)d_in[4];
    const float* b      = (const float*)d_in[5];
    float* out = (float*)d_out;

    // 1) project features: y = x @ W^T  (writes g_y directly)
    gemm_xWt<<<N_NODES / 32, 128>>>(x, W);

    // 2) out = b (broadcast)
    {
        int total = N_NODES * (F / 4);
        init_bias<<<(total + 255) / 256, 256>>>(b, out);
    }

    // 3) scatter-add edges
    {
        const int warps_per_block = 256 / 32;
        int blocks = (N_EDGES + warps_per_block - 1) / warps_per_block;
        spmm_scatter<<<blocks, 256>>>(L_rows, L_cols, L_vals, out);
    }
}

// round 3
// speedup vs baseline: 1.1504x; 1.1504x over previous
#include <cuda_runtime.h>
#include <cuda_bf16.h>
#include <cstdint>

#define N_NODES 100000
#define N_EDGES 3200000
#define F 128

// Scratch (static device globals; ~77 MB total)
__device__ float g_y[(size_t)N_NODES * F];          // projected features x@W^T (51.2 MB)
__device__ int   g_counts[N_NODES];                 // per-row degree
__device__ int   g_rowptr[N_NODES + 1];             // CSR offsets
__device__ int   g_cursor[N_NODES];                 // scatter cursors
__device__ int2  g_edges[N_EDGES];                  // (col, val-bits) sorted by row (25.6 MB)

// ---------------------------------------------------------------------------
// Kernel 1: y = x @ W^T.  Thread t owns output column t, W[t][:] in 32 float4
// regs; processes 4 rows at a time with 4 independent accumulators to break
// the FFMA RAW chain (R2 post-mortem: serial acc = 512cyc latency vs 256 issue).
// ---------------------------------------------------------------------------
__global__ __launch_bounds__(128) void gemm_xWt(const float* __restrict__ x,
                                                const float* __restrict__ W) {
    __shared__ float xs[32 * F];  // 16 KB
    const int t = threadIdx.x;
    const int row0 = blockIdx.x * 32;

    const float4* x4 = reinterpret_cast<const float4*>(x + (size_t)row0 * F);
    float4* xs4 = reinterpret_cast<float4*>(xs);
#pragma unroll
    for (int i = 0; i < 8; i++) xs4[i * 128 + t] = x4[i * 128 + t];

    const float4* Wrow = reinterpret_cast<const float4*>(W + (size_t)t * F);
    float4 wr[32];
#pragma unroll
    for (int k = 0; k < 32; k++) wr[k] = Wrow[k];

    __syncthreads();

    for (int r = 0; r < 32; r += 4) {
        const float4* xr0 = reinterpret_cast<const float4*>(xs + (r + 0) * F);
        const float4* xr1 = reinterpret_cast<const float4*>(xs + (r + 1) * F);
        const float4* xr2 = reinterpret_cast<const float4*>(xs + (r + 2) * F);
        const float4* xr3 = reinterpret_cast<const float4*>(xs + (r + 3) * F);
        float a0 = 0.f, a1 = 0.f, a2 = 0.f, a3 = 0.f;
#pragma unroll
        for (int k = 0; k < 32; k++) {
            float4 w = wr[k];
            float4 v0 = xr0[k], v1 = xr1[k], v2 = xr2[k], v3 = xr3[k];
            a0 += w.x * v0.x + w.y * v0.y + w.z * v0.z + w.w * v0.w;
            a1 += w.x * v1.x + w.y * v1.y + w.z * v1.z + w.w * v1.w;
            a2 += w.x * v2.x + w.y * v2.y + w.z * v2.z + w.w * v2.w;
            a3 += w.x * v3.x + w.y * v3.y + w.z * v3.z + w.w * v3.w;
        }
        g_y[(size_t)(row0 + r + 0) * F + t] = a0;
        g_y[(size_t)(row0 + r + 1) * F + t] = a1;
        g_y[(size_t)(row0 + r + 2) * F + t] = a2;
        g_y[(size_t)(row0 + r + 3) * F + t] = a3;
    }
}

// ---------------------------------------------------------------------------
// CSR build: zero -> histogram -> scan -> scatter
// ---------------------------------------------------------------------------
__global__ void zero_counts() {
    int i = blockIdx.x * blockDim.x + threadIdx.x;
    if (i < N_NODES) g_counts[i] = 0;
}

__global__ void histogram(const int* __restrict__ rows) {
    int e = blockIdx.x * blockDim.x + threadIdx.x;
    if (e < N_EDGES) atomicAdd(&g_counts[rows[e]], 1);
}

// Single-block scan (1024 threads, ~98 elems/thread serial + Hillis-Steele)
__global__ __launch_bounds__(1024) void scan_counts() {
    __shared__ int partials[1024];
    const int T = 1024;
    const int tid = threadIdx.x;
    const int chunk = (N_NODES + T - 1) / T;
    const int start = tid * chunk;
    const int end = min(start + chunk, N_NODES);

    int s = 0;
    for (int i = start; i < end; i++) s += g_counts[i];
    partials[tid] = s;
    __syncthreads();

    for (int off = 1; off < T; off <<= 1) {
        int v = partials[tid];
        int add = (tid >= off) ? partials[tid - off] : 0;
        __syncthreads();
        partials[tid] = v + add;
        __syncthreads();
    }

    int base = (tid > 0) ? partials[tid - 1] : 0;
    for (int i = start; i < end; i++) {
        int c = g_counts[i];
        g_rowptr[i] = base;
        g_cursor[i] = base;
        base += c;
    }
    if (tid == T - 1) g_rowptr[N_NODES] = base;
}

__global__ void build_csr(const int* __restrict__ rows,
                          const int* __restrict__ cols,
                          const float* __restrict__ vals) {
    int e = blockIdx.x * blockDim.x + threadIdx.x;
    if (e < N_EDGES) {
        int r = rows[e];
        int pos = atomicAdd(&g_cursor[r], 1);
        g_edges[pos] = make_int2(cols[e], __float_as_int(vals[e]));
    }
}

// ---------------------------------------------------------------------------
// CSR SpMM: one warp per output row. acc starts at bias; gather y rows from
// L2; exactly one streaming write of out. No atomics. 2-way unroll for MLP.
// ---------------------------------------------------------------------------
__global__ __launch_bounds__(256) void spmm_csr(const float* __restrict__ b,
                                                float* __restrict__ out) {
    const int warp = (blockIdx.x * blockDim.x + threadIdx.x) >> 5;
    const int lane = threadIdx.x & 31;
    if (warp >= N_NODES) return;

    const int beg = g_rowptr[warp];
    const int end = g_rowptr[warp + 1];

    float4 acc = reinterpret_cast<const float4*>(b)[lane];

    int i = beg;
    for (; i + 2 <= end; i += 2) {
        int2 e0 = g_edges[i];
        int2 e1 = g_edges[i + 1];
        float4 m0 = reinterpret_cast<const float4*>(g_y + (size_t)e0.x * F)[lane];
        float4 m1 = reinterpret_cast<const float4*>(g_y + (size_t)e1.x * F)[lane];
        float v0 = __int_as_float(e0.y);
        float v1 = __int_as_float(e1.y);
        acc.x += v0 * m0.x; acc.y += v0 * m0.y; acc.z += v0 * m0.z; acc.w += v0 * m0.w;
        acc.x += v1 * m1.x; acc.y += v1 * m1.y; acc.z += v1 * m1.z; acc.w += v1 * m1.w;
    }
    if (i < end) {
        int2 e0 = g_edges[i];
        float4 m0 = reinterpret_cast<const float4*>(g_y + (size_t)e0.x * F)[lane];
        float v0 = __int_as_float(e0.y);
        acc.x += v0 * m0.x; acc.y += v0 * m0.y; acc.z += v0 * m0.z; acc.w += v0 * m0.w;
    }

    reinterpret_cast<float4*>(out + (size_t)warp * F)[lane] = acc;
}

// ---------------------------------------------------------------------------
extern "C" void kernel_launch(void* const* d_in, const int* in_sizes, int n_in,
                              void* d_out, int out_size) {
    const int*   L_rows = (const int*)d_in[0];
    const int*   L_cols = (const int*)d_in[1];
    const float* L_vals = (const float*)d_in[2];
    const float* x      = (const float*)d_in[3];
    const float* W      = (const float*)d_in[4];
    const float* b      = (const float*)d_in[5];
    float* out = (float*)d_out;

    // CSR build chain
    zero_counts<<<(N_NODES + 255) / 256, 256>>>();
    histogram<<<(N_EDGES + 255) / 256, 256>>>(L_rows);
    scan_counts<<<1, 1024>>>();
    build_csr<<<(N_EDGES + 255) / 256, 256>>>(L_rows, L_cols, L_vals);

    // Feature projection y = x @ W^T
    gemm_xWt<<<N_NODES / 32, 128>>>(x, W);

    // CSR SpMM with fused bias, one warp per row
    {
        const int warps_per_block = 256 / 32;
        int blocks = (N_NODES + warps_per_block - 1) / warps_per_block;
        spmm_csr<<<blocks, 256>>>(b, out);
    }
}

// round 4
// speedup vs baseline: 1.1510x; 1.0005x over previous
#include <cuda_runtime.h>
#include <cuda_bf16.h>
#include <cstdint>

#define N_NODES 100000
#define N_EDGES 3200000
#define F 128

// Scratch (static device globals; ~77 MB total)
__device__ float g_y[(size_t)N_NODES * F];          // projected features x@W^T (51.2 MB)
__device__ int   g_counts[N_NODES];                 // per-row degree
__device__ int   g_rowptr[N_NODES + 1];             // CSR offsets
__device__ int   g_cursor[N_NODES];                 // scatter cursors
__device__ int2  g_edges[N_EDGES];                  // (col, val-bits) sorted by row (25.6 MB)

// ---------------------------------------------------------------------------
// Kernel 1: y = x @ W^T.  Thread t owns output column t, W[t][:] in 32 float4
// regs; processes 4 rows at a time with 4 independent accumulators to break
// the FFMA RAW chain (R2 post-mortem: serial acc = 512cyc latency vs 256 issue).
// ---------------------------------------------------------------------------
__global__ __launch_bounds__(128) void gemm_xWt(const float* __restrict__ x,
                                                const float* __restrict__ W) {
    __shared__ float xs[32 * F];  // 16 KB
    const int t = threadIdx.x;
    const int row0 = blockIdx.x * 32;

    const float4* x4 = reinterpret_cast<const float4*>(x + (size_t)row0 * F);
    float4* xs4 = reinterpret_cast<float4*>(xs);
#pragma unroll
    for (int i = 0; i < 8; i++) xs4[i * 128 + t] = x4[i * 128 + t];

    const float4* Wrow = reinterpret_cast<const float4*>(W + (size_t)t * F);
    float4 wr[32];
#pragma unroll
    for (int k = 0; k < 32; k++) wr[k] = Wrow[k];

    __syncthreads();

    for (int r = 0; r < 32; r += 4) {
        const float4* xr0 = reinterpret_cast<const float4*>(xs + (r + 0) * F);
        const float4* xr1 = reinterpret_cast<const float4*>(xs + (r + 1) * F);
        const float4* xr2 = reinterpret_cast<const float4*>(xs + (r + 2) * F);
        const float4* xr3 = reinterpret_cast<const float4*>(xs + (r + 3) * F);
        float a0 = 0.f, a1 = 0.f, a2 = 0.f, a3 = 0.f;
#pragma unroll
        for (int k = 0; k < 32; k++) {
            float4 w = wr[k];
            float4 v0 = xr0[k], v1 = xr1[k], v2 = xr2[k], v3 = xr3[k];
            a0 += w.x * v0.x + w.y * v0.y + w.z * v0.z + w.w * v0.w;
            a1 += w.x * v1.x + w.y * v1.y + w.z * v1.z + w.w * v1.w;
            a2 += w.x * v2.x + w.y * v2.y + w.z * v2.z + w.w * v2.w;
            a3 += w.x * v3.x + w.y * v3.y + w.z * v3.z + w.w * v3.w;
        }
        g_y[(size_t)(row0 + r + 0) * F + t] = a0;
        g_y[(size_t)(row0 + r + 1) * F + t] = a1;
        g_y[(size_t)(row0 + r + 2) * F + t] = a2;
        g_y[(size_t)(row0 + r + 3) * F + t] = a3;
    }
}

// ---------------------------------------------------------------------------
// CSR build: zero -> histogram -> scan -> scatter
// ---------------------------------------------------------------------------
__global__ void zero_counts() {
    int i = blockIdx.x * blockDim.x + threadIdx.x;
    if (i < N_NODES) g_counts[i] = 0;
}

__global__ void histogram(const int* __restrict__ rows) {
    int e = blockIdx.x * blockDim.x + threadIdx.x;
    if (e < N_EDGES) atomicAdd(&g_counts[rows[e]], 1);
}

// Single-block scan (1024 threads, ~98 elems/thread serial + Hillis-Steele)
__global__ __launch_bounds__(1024) void scan_counts() {
    __shared__ int partials[1024];
    const int T = 1024;
    const int tid = threadIdx.x;
    const int chunk = (N_NODES + T - 1) / T;
    const int start = tid * chunk;
    const int end = min(start + chunk, N_NODES);

    int s = 0;
    for (int i = start; i < end; i++) s += g_counts[i];
    partials[tid] = s;
    __syncthreads();

    for (int off = 1; off < T; off <<= 1) {
        int v = partials[tid];
        int add = (tid >= off) ? partials[tid - off] : 0;
        __syncthreads();
        partials[tid] = v + add;
        __syncthreads();
    }

    int base = (tid > 0) ? partials[tid - 1] : 0;
    for (int i = start; i < end; i++) {
        int c = g_counts[i];
        g_rowptr[i] = base;
        g_cursor[i] = base;
        base += c;
    }
    if (tid == T - 1) g_rowptr[N_NODES] = base;
}

__global__ void build_csr(const int* __restrict__ rows,
                          const int* __restrict__ cols,
                          const float* __restrict__ vals) {
    int e = blockIdx.x * blockDim.x + threadIdx.x;
    if (e < N_EDGES) {
        int r = rows[e];
        int pos = atomicAdd(&g_cursor[r], 1);
        g_edges[pos] = make_int2(cols[e], __float_as_int(vals[e]));
    }
}

// ---------------------------------------------------------------------------
// CSR SpMM: one warp per output row. acc starts at bias; gather y rows from
// L2; exactly one streaming write of out. No atomics. 2-way unroll for MLP.
// ---------------------------------------------------------------------------
__global__ __launch_bounds__(256) void spmm_csr(const float* __restrict__ b,
                                                float* __restrict__ out) {
    const int warp = (blockIdx.x * blockDim.x + threadIdx.x) >> 5;
    const int lane = threadIdx.x & 31;
    if (warp >= N_NODES) return;

    const int beg = g_rowptr[warp];
    const int end = g_rowptr[warp + 1];

    float4 acc = reinterpret_cast<const float4*>(b)[lane];

    int i = beg;
    for (; i + 2 <= end; i += 2) {
        int2 e0 = g_edges[i];
        int2 e1 = g_edges[i + 1];
        float4 m0 = reinterpret_cast<const float4*>(g_y + (size_t)e0.x * F)[lane];
        float4 m1 = reinterpret_cast<const float4*>(g_y + (size_t)e1.x * F)[lane];
        float v0 = __int_as_float(e0.y);
        float v1 = __int_as_float(e1.y);
        acc.x += v0 * m0.x; acc.y += v0 * m0.y; acc.z += v0 * m0.z; acc.w += v0 * m0.w;
        acc.x += v1 * m1.x; acc.y += v1 * m1.y; acc.z += v1 * m1.z; acc.w += v1 * m1.w;
    }
    if (i < end) {
        int2 e0 = g_edges[i];
        float4 m0 = reinterpret_cast<const float4*>(g_y + (size_t)e0.x * F)[lane];
        float v0 = __int_as_float(e0.y);
        acc.x += v0 * m0.x; acc.y += v0 * m0.y; acc.z += v0 * m0.z; acc.w += v0 * m0.w;
    }

    reinterpret_cast<float4*>(out + (size_t)warp * F)[lane] = acc;
}

// ---------------------------------------------------------------------------
extern "C" void kernel_launch(void* const* d_in, const int* in_sizes, int n_in,
                              void* d_out, int out_size) {
    const int*   L_rows = (const int*)d_in[0];
    const int*   L_cols = (const int*)d_in[1];
    const float* L_vals = (const float*)d_in[2];
    const float* x      = (const float*)d_in[3];
    const float* W      = (const float*)d_in[4];
    const float* b      = (const float*)d_in[5];
    float* out = (float*)d_out;

    // CSR build chain
    zero_counts<<<(N_NODES + 255) / 256, 256>>>();
    histogram<<<(N_EDGES + 255) / 256, 256>>>(L_rows);
    scan_counts<<<1, 1024>>>();
    build_csr<<<(N_EDGES + 255) / 256, 256>>>(L_rows, L_cols, L_vals);

    // Feature projection y = x @ W^T
    gemm_xWt<<<N_NODES / 32, 128>>>(x, W);

    // CSR SpMM with fused bias, one warp per row
    {
        const int warps_per_block = 256 / 32;
        int blocks = (N_NODES + warps_per_block - 1) / warps_per_block;
        spmm_csr<<<blocks, 256>>>(b, out);
    }
}

// round 5
// speedup vs baseline: 1.2329x; 1.0712x over previous
#include <cuda_runtime.h>
#include <cuda_bf16.h>
#include <cuda_fp16.h>
#include <cstdint>

#define N_NODES 100000
#define N_EDGES 3200000
#define F 128

// Scratch (static device globals)
__device__ __half g_y[(size_t)N_NODES * F];         // projected features, fp16 (25.6 MB)
__device__ int    g_counts[N_NODES];
__device__ int    g_rowptr[N_NODES + 1];
__device__ int    g_cursor[N_NODES];
__device__ int2   g_edges[N_EDGES];                 // (col, val-bits) grouped by row (25.6 MB)

// ---------------------------------------------------------------------------
// Kernel 1: y = x @ W^T  -> fp16.  Thread t owns output column t (W row in
// 32 float4 regs); 4 rows at a time = 4 independent FFMA chains.
// ---------------------------------------------------------------------------
__global__ __launch_bounds__(128) void gemm_xWt(const float* __restrict__ x,
                                                const float* __restrict__ W) {
    __shared__ float xs[32 * F];  // 16 KB
    const int t = threadIdx.x;
    const int row0 = blockIdx.x * 32;

    const float4* x4 = reinterpret_cast<const float4*>(x + (size_t)row0 * F);
    float4* xs4 = reinterpret_cast<float4*>(xs);
#pragma unroll
    for (int i = 0; i < 8; i++) xs4[i * 128 + t] = x4[i * 128 + t];

    const float4* Wrow = reinterpret_cast<const float4*>(W + (size_t)t * F);
    float4 wr[32];
#pragma unroll
    for (int k = 0; k < 32; k++) wr[k] = Wrow[k];

    __syncthreads();

    for (int r = 0; r < 32; r += 4) {
        const float4* xr0 = reinterpret_cast<const float4*>(xs + (r + 0) * F);
        const float4* xr1 = reinterpret_cast<const float4*>(xs + (r + 1) * F);
        const float4* xr2 = reinterpret_cast<const float4*>(xs + (r + 2) * F);
        const float4* xr3 = reinterpret_cast<const float4*>(xs + (r + 3) * F);
        float a0 = 0.f, a1 = 0.f, a2 = 0.f, a3 = 0.f;
#pragma unroll
        for (int k = 0; k < 32; k++) {
            float4 w = wr[k];
            float4 v0 = xr0[k], v1 = xr1[k], v2 = xr2[k], v3 = xr3[k];
            a0 += w.x * v0.x + w.y * v0.y + w.z * v0.z + w.w * v0.w;
            a1 += w.x * v1.x + w.y * v1.y + w.z * v1.z + w.w * v1.w;
            a2 += w.x * v2.x + w.y * v2.y + w.z * v2.z + w.w * v2.w;
            a3 += w.x * v3.x + w.y * v3.y + w.z * v3.z + w.w * v3.w;
        }
        g_y[(size_t)(row0 + r + 0) * F + t] = __float2half_rn(a0);
        g_y[(size_t)(row0 + r + 1) * F + t] = __float2half_rn(a1);
        g_y[(size_t)(row0 + r + 2) * F + t] = __float2half_rn(a2);
        g_y[(size_t)(row0 + r + 3) * F + t] = __float2half_rn(a3);
    }
}

// ---------------------------------------------------------------------------
// CSR build: zero -> histogram(x4) -> scan -> scatter(x4)
// R4 post-mortem: build_csr issue=4.9% -> latency-bound; 4 edges/thread gives
// 4 independent atomic->store chains (MLP=4).
// ---------------------------------------------------------------------------
__global__ void zero_counts() {
    int i = blockIdx.x * blockDim.x + threadIdx.x;
    if (i < N_NODES / 4) reinterpret_cast<int4*>(g_counts)[i] = make_int4(0, 0, 0, 0);
}

__global__ void histogram4(const int* __restrict__ rows) {
    int i = blockIdx.x * blockDim.x + threadIdx.x;
    if (i < N_EDGES / 4) {
        int4 r = reinterpret_cast<const int4*>(rows)[i];
        atomicAdd(&g_counts[r.x], 1);
        atomicAdd(&g_counts[r.y], 1);
        atomicAdd(&g_counts[r.z], 1);
        atomicAdd(&g_counts[r.w], 1);
    }
}

__global__ __launch_bounds__(1024) void scan_counts() {
    __shared__ int partials[1024];
    const int T = 1024;
    const int tid = threadIdx.x;
    const int chunk = (N_NODES + T - 1) / T;
    const int start = tid * chunk;
    const int end = min(start + chunk, N_NODES);

    int s = 0;
    for (int i = start; i < end; i++) s += g_counts[i];
    partials[tid] = s;
    __syncthreads();

    for (int off = 1; off < T; off <<= 1) {
        int v = partials[tid];
        int add = (tid >= off) ? partials[tid - off] : 0;
        __syncthreads();
        partials[tid] = v + add;
        __syncthreads();
    }

    int base = (tid > 0) ? partials[tid - 1] : 0;
    for (int i = start; i < end; i++) {
        int c = g_counts[i];
        g_rowptr[i] = base;
        g_cursor[i] = base;
        base += c;
    }
    if (tid == T - 1) g_rowptr[N_NODES] = base;
}

__global__ void build_csr4(const int* __restrict__ rows,
                           const int* __restrict__ cols,
                           const float* __restrict__ vals) {
    int i = blockIdx.x * blockDim.x + threadIdx.x;
    if (i < N_EDGES / 4) {
        int4   r = reinterpret_cast<const int4*>(rows)[i];
        int4   c = reinterpret_cast<const int4*>(cols)[i];
        float4 v = reinterpret_cast<const float4*>(vals)[i];
        int p0 = atomicAdd(&g_cursor[r.x], 1);
        int p1 = atomicAdd(&g_cursor[r.y], 1);
        int p2 = atomicAdd(&g_cursor[r.z], 1);
        int p3 = atomicAdd(&g_cursor[r.w], 1);
        g_edges[p0] = make_int2(c.x, __float_as_int(v.x));
        g_edges[p1] = make_int2(c.y, __float_as_int(v.y));
        g_edges[p2] = make_int2(c.z, __float_as_int(v.z));
        g_edges[p3] = make_int2(c.w, __float_as_int(v.w));
    }
}

// ---------------------------------------------------------------------------
// CSR SpMM: one warp per output row; fp16 y gather (8B/lane/edge), fp32 acc,
// bias fused, one streaming write. 4-way unrolled for MLP.
// ---------------------------------------------------------------------------
__global__ __launch_bounds__(256) void spmm_csr(const float* __restrict__ b,
                                                float* __restrict__ out) {
    const int warp = (blockIdx.x * blockDim.x + threadIdx.x) >> 5;
    const int lane = threadIdx.x & 31;
    if (warp >= N_NODES) return;

    const int beg = g_rowptr[warp];
    const int end = g_rowptr[warp + 1];

    float4 acc = reinterpret_cast<const float4*>(b)[lane];  // cols 4l..4l+3

    int i = beg;
    for (; i + 4 <= end; i += 4) {
        int2 e0 = g_edges[i];
        int2 e1 = g_edges[i + 1];
        int2 e2 = g_edges[i + 2];
        int2 e3 = g_edges[i + 3];
        uint2 p0 = reinterpret_cast<const uint2*>(g_y + (size_t)e0.x * F)[lane];
        uint2 p1 = reinterpret_cast<const uint2*>(g_y + (size_t)e1.x * F)[lane];
        uint2 p2 = reinterpret_cast<const uint2*>(g_y + (size_t)e2.x * F)[lane];
        uint2 p3 = reinterpret_cast<const uint2*>(g_y + (size_t)e3.x * F)[lane];
#pragma unroll
        for (int j = 0; j < 4; j++) {
            uint2 p = (j == 0) ? p0 : (j == 1) ? p1 : (j == 2) ? p2 : p3;
            float v = __int_as_float((j == 0) ? e0.y : (j == 1) ? e1.y : (j == 2) ? e2.y : e3.y);
            float2 lo = __half22float2(*reinterpret_cast<__half2*>(&p.x));
            float2 hi = __half22float2(*reinterpret_cast<__half2*>(&p.y));
            acc.x += v * lo.x; acc.y += v * lo.y; acc.z += v * hi.x; acc.w += v * hi.y;
        }
    }
    for (; i < end; i++) {
        int2 e0 = g_edges[i];
        uint2 p = reinterpret_cast<const uint2*>(g_y + (size_t)e0.x * F)[lane];
        float v = __int_as_float(e0.y);
        float2 lo = __half22float2(*reinterpret_cast<__half2*>(&p.x));
        float2 hi = __half22float2(*reinterpret_cast<__half2*>(&p.y));
        acc.x += v * lo.x; acc.y += v * lo.y; acc.z += v * hi.x; acc.w += v * hi.y;
    }

    reinterpret_cast<float4*>(out + (size_t)warp * F)[lane] = acc;
}

// ---------------------------------------------------------------------------
extern "C" void kernel_launch(void* const* d_in, const int* in_sizes, int n_in,
                              void* d_out, int out_size) {
    const int*   L_rows = (const int*)d_in[0];
    const int*   L_cols = (const int*)d_in[1];
    const float* L_vals = (const float*)d_in[2];
    const float* x      = (const float*)d_in[3];
    const float* W      = (const float*)d_in[4];
    const float* b      = (const float*)d_in[5];
    float* out = (float*)d_out;

    zero_counts<<<(N_NODES / 4 + 255) / 256, 256>>>();
    histogram4<<<(N_EDGES / 4 + 255) / 256, 256>>>(L_rows);
    scan_counts<<<1, 1024>>>();
    build_csr4<<<(N_EDGES / 4 + 255) / 256, 256>>>(L_rows, L_cols, L_vals);

    gemm_xWt<<<N_NODES / 32, 128>>>(x, W);

    {
        const int warps_per_block = 256 / 32;
        int blocks = (N_NODES + warps_per_block - 1) / warps_per_block;
        spmm_csr<<<blocks, 256>>>(b, out);
    }
}

// round 6
// speedup vs baseline: 1.6789x; 1.3617x over previous
#include <cuda_runtime.h>
#include <cuda_bf16.h>
#include <cuda_fp16.h>
#include <cstdint>

#define N_NODES 100000
#define N_EDGES 3200000
#define F 128

// Scratch (static device globals)
__device__ __half g_y[(size_t)N_NODES * F];         // projected features, fp16 (25.6 MB)
__device__ int    g_counts[N_NODES];
__device__ int    g_rowptr[N_NODES + 1];
__device__ int    g_cursor[N_NODES];
__device__ int2   g_edges[N_EDGES];                 // (col, val-bits) grouped by row

// ---------------------------------------------------------------------------
// Kernel 1: y = x @ W^T via tensor cores (mma.sync m16n8k16 f16f16f32).
// Block = 128 thr (4 warps), each warp computes a 16-row x 128-col tile.
// W is converted fp32->fp16 into smem once per block (stride 136 halfs kills
// bank conflicts on B-fragment loads). A fragments come straight from global
// fp32 x as float2 -> half2 (x read exactly once, coalesced).
// ---------------------------------------------------------------------------
#define WS_STRIDE 136

__global__ __launch_bounds__(128) void gemm_mma(const float* __restrict__ x,
                                                const float* __restrict__ W) {
    __shared__ __half Ws[128 * WS_STRIDE];  // 34.8 KB

    const int tid  = threadIdx.x;
    const int warp = tid >> 5;
    const int lane = tid & 31;
    const int g    = lane >> 2;   // group id 0..7
    const int tig  = lane & 3;    // thread in group

    // Convert W (128x128 fp32) into Ws fp16
    const float4* W4 = reinterpret_cast<const float4*>(W);
#pragma unroll
    for (int i = 0; i < 32; i++) {
        int idx = i * 128 + tid;          // float4 index
        float4 v = W4[idx];
        int flat = idx * 4;
        int n = flat >> 7, k = flat & 127;
        __half2* dst = reinterpret_cast<__half2*>(&Ws[n * WS_STRIDE + k]);
        dst[0] = __floats2half2_rn(v.x, v.y);
        dst[1] = __floats2half2_rn(v.z, v.w);
    }
    __syncthreads();

    const int row0 = blockIdx.x * 64 + warp * 16;
    const int r_lo = row0 + g;
    const int r_hi = row0 + g + 8;
    const bool st_lo = r_lo < N_NODES;
    const bool st_hi = r_hi < N_NODES;
    const float* xlo = x + (size_t)(st_lo ? r_lo : N_NODES - 1) * F;
    const float* xhi = x + (size_t)(st_hi ? r_hi : N_NODES - 1) * F;

    float acc[16][4];
#pragma unroll
    for (int nt = 0; nt < 16; nt++)
#pragma unroll
        for (int j = 0; j < 4; j++) acc[nt][j] = 0.f;

#pragma unroll
    for (int kt = 0; kt < 8; kt++) {
        const int kb = kt * 16 + tig * 2;
        float2 f0 = *reinterpret_cast<const float2*>(xlo + kb);
        float2 f1 = *reinterpret_cast<const float2*>(xhi + kb);
        float2 f2 = *reinterpret_cast<const float2*>(xlo + kb + 8);
        float2 f3 = *reinterpret_cast<const float2*>(xhi + kb + 8);
        __half2 h0 = __floats2half2_rn(f0.x, f0.y);
        __half2 h1 = __floats2half2_rn(f1.x, f1.y);
        __half2 h2v = __floats2half2_rn(f2.x, f2.y);
        __half2 h3 = __floats2half2_rn(f3.x, f3.y);
        uint32_t a0 = *reinterpret_cast<uint32_t*>(&h0);
        uint32_t a1 = *reinterpret_cast<uint32_t*>(&h1);
        uint32_t a2 = *reinterpret_cast<uint32_t*>(&h2v);
        uint32_t a3 = *reinterpret_cast<uint32_t*>(&h3);

        const __half* wk = &Ws[kt * 16 + tig * 2];
#pragma unroll
        for (int nt = 0; nt < 16; nt++) {
            const __half* wp = wk + (nt * 8 + g) * WS_STRIDE;
            uint32_t b0 = *reinterpret_cast<const uint32_t*>(wp);
            uint32_t b1 = *reinterpret_cast<const uint32_t*>(wp + 8);
            asm volatile(
                "mma.sync.aligned.m16n8k16.row.col.f32.f16.f16.f32 "
                "{%0,%1,%2,%3}, {%4,%5,%6,%7}, {%8,%9}, {%0,%1,%2,%3};"
                : "+f"(acc[nt][0]), "+f"(acc[nt][1]), "+f"(acc[nt][2]), "+f"(acc[nt][3])
                : "r"(a0), "r"(a1), "r"(a2), "r"(a3), "r"(b0), "r"(b1));
        }
    }

    // Store y fp16 (c0,c1 -> row g; c2,c3 -> row g+8; cols nt*8 + tig*2 .. +1)
#pragma unroll
    for (int nt = 0; nt < 16; nt++) {
        int n = nt * 8 + tig * 2;
        if (st_lo)
            *reinterpret_cast<__half2*>(&g_y[(size_t)r_lo * F + n]) =
                __floats2half2_rn(acc[nt][0], acc[nt][1]);
        if (st_hi)
            *reinterpret_cast<__half2*>(&g_y[(size_t)r_hi * F + n]) =
                __floats2half2_rn(acc[nt][2], acc[nt][3]);
    }
}

// ---------------------------------------------------------------------------
// CSR build: zero -> histogram(x4) -> scan -> scatter(x4)
// ---------------------------------------------------------------------------
__global__ void zero_counts() {
    int i = blockIdx.x * blockDim.x + threadIdx.x;
    if (i < N_NODES / 4) reinterpret_cast<int4*>(g_counts)[i] = make_int4(0, 0, 0, 0);
}

__global__ void histogram4(const int* __restrict__ rows) {
    int i = blockIdx.x * blockDim.x + threadIdx.x;
    if (i < N_EDGES / 4) {
        int4 r = reinterpret_cast<const int4*>(rows)[i];
        atomicAdd(&g_counts[r.x], 1);
        atomicAdd(&g_counts[r.y], 1);
        atomicAdd(&g_counts[r.z], 1);
        atomicAdd(&g_counts[r.w], 1);
    }
}

__global__ __launch_bounds__(1024) void scan_counts() {
    __shared__ int partials[1024];
    const int T = 1024;
    const int tid = threadIdx.x;
    const int chunk = (N_NODES + T - 1) / T;
    const int start = tid * chunk;
    const int end = min(start + chunk, N_NODES);

    int s = 0;
    for (int i = start; i < end; i++) s += g_counts[i];
    partials[tid] = s;
    __syncthreads();

    for (int off = 1; off < T; off <<= 1) {
        int v = partials[tid];
        int add = (tid >= off) ? partials[tid - off] : 0;
        __syncthreads();
        partials[tid] = v + add;
        __syncthreads();
    }

    int base = (tid > 0) ? partials[tid - 1] : 0;
    for (int i = start; i < end; i++) {
        int c = g_counts[i];
        g_rowptr[i] = base;
        g_cursor[i] = base;
        base += c;
    }
    if (tid == T - 1) g_rowptr[N_NODES] = base;
}

__global__ void build_csr4(const int* __restrict__ rows,
                           const int* __restrict__ cols,
                           const float* __restrict__ vals) {
    int i = blockIdx.x * blockDim.x + threadIdx.x;
    if (i < N_EDGES / 4) {
        int4   r = reinterpret_cast<const int4*>(rows)[i];
        int4   c = reinterpret_cast<const int4*>(cols)[i];
        float4 v = reinterpret_cast<const float4*>(vals)[i];
        int p0 = atomicAdd(&g_cursor[r.x], 1);
        int p1 = atomicAdd(&g_cursor[r.y], 1);
        int p2 = atomicAdd(&g_cursor[r.z], 1);
        int p3 = atomicAdd(&g_cursor[r.w], 1);
        g_edges[p0] = make_int2(c.x, __float_as_int(v.x));
        g_edges[p1] = make_int2(c.y, __float_as_int(v.y));
        g_edges[p2] = make_int2(c.z, __float_as_int(v.z));
        g_edges[p3] = make_int2(c.w, __float_as_int(v.w));
    }
}

// ---------------------------------------------------------------------------
// CSR SpMM: one warp per output row; fp16 y gather, fp32 acc, bias fused.
// 8-way unrolled: 8 independent gathers batched ahead of the reduction.
// ---------------------------------------------------------------------------
__global__ __launch_bounds__(256) void spmm_csr(const float* __restrict__ b,
                                                float* __restrict__ out) {
    const int warp = (blockIdx.x * blockDim.x + threadIdx.x) >> 5;
    const int lane = threadIdx.x & 31;
    if (warp >= N_NODES) return;

    const int beg = g_rowptr[warp];
    const int end = g_rowptr[warp + 1];

    float4 acc = reinterpret_cast<const float4*>(b)[lane];

    int i = beg;
    for (; i + 8 <= end; i += 8) {
        int   c[8];
        float v[8];
        uint2 p[8];
#pragma unroll
        for (int j = 0; j < 8; j++) {
            int2 e = g_edges[i + j];
            c[j] = e.x;
            v[j] = __int_as_float(e.y);
        }
#pragma unroll
        for (int j = 0; j < 8; j++)
            p[j] = reinterpret_cast<const uint2*>(g_y + (size_t)c[j] * F)[lane];
#pragma unroll
        for (int j = 0; j < 8; j++) {
            float2 lo = __half22float2(*reinterpret_cast<__half2*>(&p[j].x));
            float2 hi = __half22float2(*reinterpret_cast<__half2*>(&p[j].y));
            acc.x += v[j] * lo.x; acc.y += v[j] * lo.y;
            acc.z += v[j] * hi.x; acc.w += v[j] * hi.y;
        }
    }
    for (; i < end; i++) {
        int2 e = g_edges[i];
        uint2 p = reinterpret_cast<const uint2*>(g_y + (size_t)e.x * F)[lane];
        float v = __int_as_float(e.y);
        float2 lo = __half22float2(*reinterpret_cast<__half2*>(&p.x));
        float2 hi = __half22float2(*reinterpret_cast<__half2*>(&p.y));
        acc.x += v * lo.x; acc.y += v * lo.y;
        acc.z += v * hi.x; acc.w += v * hi.y;
    }

    reinterpret_cast<float4*>(out + (size_t)warp * F)[lane] = acc;
}

// ---------------------------------------------------------------------------
extern "C" void kernel_launch(void* const* d_in, const int* in_sizes, int n_in,
                              void* d_out, int out_size) {
    const int*   L_rows = (const int*)d_in[0];
    const int*   L_cols = (const int*)d_in[1];
    const float* L_vals = (const float*)d_in[2];
    const float* x      = (const float*)d_in[3];
    const float* W      = (const float*)d_in[4];
    const float* b      = (const float*)d_in[5];
    float* out = (float*)d_out;

    zero_counts<<<(N_NODES / 4 + 255) / 256, 256>>>();
    histogram4<<<(N_EDGES / 4 + 255) / 256, 256>>>(L_rows);
    scan_counts<<<1, 1024>>>();
    build_csr4<<<(N_EDGES / 4 + 255) / 256, 256>>>(L_rows, L_cols, L_vals);

    gemm_mma<<<(N_NODES + 63) / 64, 128>>>(x, W);

    {
        const int warps_per_block = 256 / 32;
        int blocks = (N_NODES + warps_per_block - 1) / warps_per_block;
        spmm_csr<<<blocks, 256>>>(b, out);
    }
}

// round 7
// speedup vs baseline: 2.0650x; 1.2299x over previous
#include <cuda_runtime.h>
#include <cuda_bf16.h>
#include <cuda_fp16.h>
#include <cstdint>

#define N_NODES 100000
#define N_EDGES 3200000
#define F 128

// Scratch (static device globals)
__device__ __half g_y[(size_t)N_NODES * F];   // projected features fp16 (25.6 MB)
__device__ int    g_counts[N_NODES];
__device__ int    g_rowptr[N_NODES + 1];
__device__ int    g_rank[N_EDGES];            // rank of edge within its row (12.8 MB)
__device__ int2   g_edges[N_EDGES];           // (col, val-bits) grouped by row (25.6 MB)

// ---------------------------------------------------------------------------
// Kernel 1: y = x @ W^T via tensor cores (mma.sync m16n8k16 f16f16f32).
// ---------------------------------------------------------------------------
#define WS_STRIDE 136

__global__ __launch_bounds__(128) void gemm_mma(const float* __restrict__ x,
                                                const float* __restrict__ W) {
    __shared__ __half Ws[128 * WS_STRIDE];  // 34.8 KB

    const int tid  = threadIdx.x;
    const int warp = tid >> 5;
    const int lane = tid & 31;
    const int g    = lane >> 2;
    const int tig  = lane & 3;

    const float4* W4 = reinterpret_cast<const float4*>(W);
#pragma unroll
    for (int i = 0; i < 32; i++) {
        int idx = i * 128 + tid;
        float4 v = W4[idx];
        int flat = idx * 4;
        int n = flat >> 7, k = flat & 127;
        __half2* dst = reinterpret_cast<__half2*>(&Ws[n * WS_STRIDE + k]);
        dst[0] = __floats2half2_rn(v.x, v.y);
        dst[1] = __floats2half2_rn(v.z, v.w);
    }
    __syncthreads();

    const int row0 = blockIdx.x * 64 + warp * 16;
    const int r_lo = row0 + g;
    const int r_hi = row0 + g + 8;
    const bool st_lo = r_lo < N_NODES;
    const bool st_hi = r_hi < N_NODES;
    const float* xlo = x + (size_t)(st_lo ? r_lo : N_NODES - 1) * F;
    const float* xhi = x + (size_t)(st_hi ? r_hi : N_NODES - 1) * F;

    float acc[16][4];
#pragma unroll
    for (int nt = 0; nt < 16; nt++)
#pragma unroll
        for (int j = 0; j < 4; j++) acc[nt][j] = 0.f;

#pragma unroll
    for (int kt = 0; kt < 8; kt++) {
        const int kb = kt * 16 + tig * 2;
        float2 f0 = *reinterpret_cast<const float2*>(xlo + kb);
        float2 f1 = *reinterpret_cast<const float2*>(xhi + kb);
        float2 f2 = *reinterpret_cast<const float2*>(xlo + kb + 8);
        float2 f3 = *reinterpret_cast<const float2*>(xhi + kb + 8);
        __half2 h0 = __floats2half2_rn(f0.x, f0.y);
        __half2 h1 = __floats2half2_rn(f1.x, f1.y);
        __half2 h2v = __floats2half2_rn(f2.x, f2.y);
        __half2 h3 = __floats2half2_rn(f3.x, f3.y);
        uint32_t a0 = *reinterpret_cast<uint32_t*>(&h0);
        uint32_t a1 = *reinterpret_cast<uint32_t*>(&h1);
        uint32_t a2 = *reinterpret_cast<uint32_t*>(&h2v);
        uint32_t a3 = *reinterpret_cast<uint32_t*>(&h3);

        const __half* wk = &Ws[kt * 16 + tig * 2];
#pragma unroll
        for (int nt = 0; nt < 16; nt++) {
            const __half* wp = wk + (nt * 8 + g) * WS_STRIDE;
            uint32_t b0 = *reinterpret_cast<const uint32_t*>(wp);
            uint32_t b1 = *reinterpret_cast<const uint32_t*>(wp + 8);
            asm volatile(
                "mma.sync.aligned.m16n8k16.row.col.f32.f16.f16.f32 "
                "{%0,%1,%2,%3}, {%4,%5,%6,%7}, {%8,%9}, {%0,%1,%2,%3};"
                : "+f"(acc[nt][0]), "+f"(acc[nt][1]), "+f"(acc[nt][2]), "+f"(acc[nt][3])
                : "r"(a0), "r"(a1), "r"(a2), "r"(a3), "r"(b0), "r"(b1));
        }
    }

#pragma unroll
    for (int nt = 0; nt < 16; nt++) {
        int n = nt * 8 + tig * 2;
        if (st_lo)
            *reinterpret_cast<__half2*>(&g_y[(size_t)r_lo * F + n]) =
                __floats2half2_rn(acc[nt][0], acc[nt][1]);
        if (st_hi)
            *reinterpret_cast<__half2*>(&g_y[(size_t)r_hi * F + n]) =
                __floats2half2_rn(acc[nt][2], acc[nt][3]);
    }
}

// ---------------------------------------------------------------------------
// CSR build, restructured (R6 post-mortem: build_csr4 was bound by the
// atomic->dependent-scattered-store chain, issue=2%):
//   pass1: rank[e] = atomicAdd(count[row],1)   (rank store is streaming)
//   scan:  rowptr = exclusive_scan(count)
//   pass2: edges[rowptr[row]+rank] = (col,val)  (NO atomics, independent STGs)
// ---------------------------------------------------------------------------
__global__ void zero_counts() {
    int i = blockIdx.x * blockDim.x + threadIdx.x;
    if (i < N_NODES / 4) reinterpret_cast<int4*>(g_counts)[i] = make_int4(0, 0, 0, 0);
}

__global__ void hist_rank4(const int* __restrict__ rows) {
    int i = blockIdx.x * blockDim.x + threadIdx.x;
    if (i < N_EDGES / 4) {
        int4 r = reinterpret_cast<const int4*>(rows)[i];
        int4 k;
        k.x = atomicAdd(&g_counts[r.x], 1);
        k.y = atomicAdd(&g_counts[r.y], 1);
        k.z = atomicAdd(&g_counts[r.z], 1);
        k.w = atomicAdd(&g_counts[r.w], 1);
        reinterpret_cast<int4*>(g_rank)[i] = k;
    }
}

__global__ __launch_bounds__(1024) void scan_counts() {
    __shared__ int partials[1024];
    const int T = 1024;
    const int tid = threadIdx.x;
    const int chunk = (N_NODES + T - 1) / T;
    const int start = tid * chunk;
    const int end = min(start + chunk, N_NODES);

    int s = 0;
    for (int i = start; i < end; i++) s += g_counts[i];
    partials[tid] = s;
    __syncthreads();

    for (int off = 1; off < T; off <<= 1) {
        int v = partials[tid];
        int add = (tid >= off) ? partials[tid - off] : 0;
        __syncthreads();
        partials[tid] = v + add;
        __syncthreads();
    }

    int base = (tid > 0) ? partials[tid - 1] : 0;
    for (int i = start; i < end; i++) {
        int c = g_counts[i];
        g_rowptr[i] = base;
        base += c;
    }
    if (tid == T - 1) g_rowptr[N_NODES] = base;
}

__global__ void place4(const int* __restrict__ rows,
                       const int* __restrict__ cols,
                       const float* __restrict__ vals) {
    int i = blockIdx.x * blockDim.x + threadIdx.x;
    if (i < N_EDGES / 4) {
        int4   r = reinterpret_cast<const int4*>(rows)[i];
        int4   c = reinterpret_cast<const int4*>(cols)[i];
        float4 v = reinterpret_cast<const float4*>(vals)[i];
        int4   k = reinterpret_cast<const int4*>(g_rank)[i];
        g_edges[g_rowptr[r.x] + k.x] = make_int2(c.x, __float_as_int(v.x));
        g_edges[g_rowptr[r.y] + k.y] = make_int2(c.y, __float_as_int(v.y));
        g_edges[g_rowptr[r.z] + k.z] = make_int2(c.z, __float_as_int(v.z));
        g_edges[g_rowptr[r.w] + k.w] = make_int2(c.w, __float_as_int(v.w));
    }
}

// ---------------------------------------------------------------------------
// CSR SpMM: one warp per row. Edge list for the row is staged into smem with
// one cooperative coalesced load (removes per-iteration edge->gather dependent
// chain), then gathers issue 16-deep. fp32 acc, bias fused, single write.
// ---------------------------------------------------------------------------
#define MAX_STAGE 96   // P(Poisson(32) > 96) ~ 1e-18; chunk loop handles rest

__global__ __launch_bounds__(256) void spmm_csr(const float* __restrict__ b,
                                                float* __restrict__ out) {
    __shared__ int2 es[8][MAX_STAGE];  // 6 KB
    const int warp = (blockIdx.x * blockDim.x + threadIdx.x) >> 5;
    const int w    = (threadIdx.x >> 5) & 7;
    const int lane = threadIdx.x & 31;
    if (warp >= N_NODES) return;

    const int beg = g_rowptr[warp];
    const int end = g_rowptr[warp + 1];

    float4 acc = reinterpret_cast<const float4*>(b)[lane];

    int i = beg;
    while (i < end) {
        const int n = min(end - i, MAX_STAGE);
        // cooperative staged load of the edge list (coalesced int2)
        for (int j = lane; j < n; j += 32) es[w][j] = g_edges[i + j];
        __syncwarp();

        int j = 0;
        for (; j + 16 <= n; j += 16) {
            uint2 p[16];
            float v[16];
#pragma unroll
            for (int q = 0; q < 16; q++) {
                int2 e = es[w][j + q];
                v[q] = __int_as_float(e.y);
                p[q] = reinterpret_cast<const uint2*>(g_y + (size_t)e.x * F)[lane];
            }
#pragma unroll
            for (int q = 0; q < 16; q++) {
                float2 lo = __half22float2(*reinterpret_cast<__half2*>(&p[q].x));
                float2 hi = __half22float2(*reinterpret_cast<__half2*>(&p[q].y));
                acc.x += v[q] * lo.x; acc.y += v[q] * lo.y;
                acc.z += v[q] * hi.x; acc.w += v[q] * hi.y;
            }
        }
        for (; j + 4 <= n; j += 4) {
            uint2 p[4];
            float v[4];
#pragma unroll
            for (int q = 0; q < 4; q++) {
                int2 e = es[w][j + q];
                v[q] = __int_as_float(e.y);
                p[q] = reinterpret_cast<const uint2*>(g_y + (size_t)e.x * F)[lane];
            }
#pragma unroll
            for (int q = 0; q < 4; q++) {
                float2 lo = __half22float2(*reinterpret_cast<__half2*>(&p[q].x));
                float2 hi = __half22float2(*reinterpret_cast<__half2*>(&p[q].y));
                acc.x += v[q] * lo.x; acc.y += v[q] * lo.y;
                acc.z += v[q] * hi.x; acc.w += v[q] * hi.y;
            }
        }
        for (; j < n; j++) {
            int2 e = es[w][j];
            uint2 p = reinterpret_cast<const uint2*>(g_y + (size_t)e.x * F)[lane];
            float v = __int_as_float(e.y);
            float2 lo = __half22float2(*reinterpret_cast<__half2*>(&p.x));
            float2 hi = __half22float2(*reinterpret_cast<__half2*>(&p.y));
            acc.x += v * lo.x; acc.y += v * lo.y;
            acc.z += v * hi.x; acc.w += v * hi.y;
        }
        i += n;
        __syncwarp();
    }

    reinterpret_cast<float4*>(out + (size_t)warp * F)[lane] = acc;
}

// ---------------------------------------------------------------------------
extern "C" void kernel_launch(void* const* d_in, const int* in_sizes, int n_in,
                              void* d_out, int out_size) {
    const int*   L_rows = (const int*)d_in[0];
    const int*   L_cols = (const int*)d_in[1];
    const float* L_vals = (const float*)d_in[2];
    const float* x      = (const float*)d_in[3];
    const float* W      = (const float*)d_in[4];
    const float* b      = (const float*)d_in[5];
    float* out = (float*)d_out;

    zero_counts<<<(N_NODES / 4 + 255) / 256, 256>>>();
    hist_rank4<<<(N_EDGES / 4 + 255) / 256, 256>>>(L_rows);
    scan_counts<<<1, 1024>>>();
    place4<<<(N_EDGES / 4 + 255) / 256, 256>>>(L_rows, L_cols, L_vals);

    gemm_mma<<<(N_NODES + 63) / 64, 128>>>(x, W);

    {
        const int warps_per_block = 256 / 32;
        int blocks = (N_NODES + warps_per_block - 1) / warps_per_block;
        spmm_csr<<<blocks, 256>>>(b, out);
    }
}